// round 16
// baseline (speedup 1.0000x reference)
#include <cuda_runtime.h>

// Fully-fused 4-level 2D Haar DWT — single-wave, warp-register L1->L2 fusion.
// Input x: (32, 3, 512, 512) fp32.
// Output: concat of t1 (32,12,256,256), t2 (32,12,128,128),
//         t3 (32,12,64,64), t4 (32,12,32,32).
//
// One block = one 128x128 input tile. Each warp computes TWO adjacent L1
// output rows per iteration; each lane then holds the 2x2 L1-LL quad for one
// L2 output pixel in registers -> L2 computed with ZERO shared memory and
// zero shuffles. Only L2-LL (4KB) and L3-LL (1KB) are staged in smem.
// 128 threads, ~5KB smem, launch_bounds(128,11): 11 blocks/SM x 148 SMs =
// 1628 >= 1536 grid blocks -> the ENTIRE grid is resident in one wave
// (previous best had 1.3-1.5 waves; the partial wave was the residual tail).
// Level 4 computes r,g only (b4 = g4 duplicated into channels 8..11).

#define HAAR(a_, b_, c_, d_, LL, LH, HL, HH)      \
    do {                                          \
        float L0 = (a_ + c_) * 0.5f;              \
        float L1 = (b_ + d_) * 0.5f;              \
        float H0 = fabsf(a_ - c_);                \
        float H1 = fabsf(b_ - d_);                \
        LL = (L0 + L1) * 0.5f;                    \
        LH = fabsf(L0 - L1);                      \
        HL = (H0 + H1) * 0.5f;                    \
        HH = fabsf(H0 - H1);                      \
    } while (0)

__global__ __launch_bounds__(128, 11) void dwt_fused_kernel(
    const float* __restrict__ x, float* __restrict__ out)
{
    __shared__ float s2[32 * 32];   // 4 KB, L2 LL
    __shared__ float s3[16 * 16];   // 1 KB, L3 LL

    const int tid  = threadIdx.x;
    const int lane = tid & 31;
    const int w    = tid >> 5;        // warp 0..3
    const int tj   = blockIdx.x;      // 0..3 (column tile)
    const int ti   = blockIdx.y;      // 0..3 (row tile)
    const int bc   = blockIdx.z;      // 0..95
    const int b    = bc / 3;
    const int c    = bc % 3;

    const long S1 = 32L * 12 * 256 * 256;
    const long S2 = 32L * 12 * 128 * 128;
    const long S3 = 32L * 12 * 64 * 64;

    // ---- Phase A: fused Level1 + Level2 (per-warp, register cascade) -----
    {
        const float* ip = x + (long)b * (3 * 512 * 512)
                            + (long)c * (512 * 512)
                            + (long)(ti * 128) * 512 + tj * 128;
        float* o1 = out + (long)b * (12 * 65536)
                        + (long)(c * 4) * 65536
                        + (long)(ti * 64) * 256 + tj * 64;
        float* o2 = out + S1 + (long)b * (12 * 16384)
                        + (long)(c * 4) * 16384
                        + (long)(ti * 32) * 128 + tj * 32;

        // Warp w handles L2 output rows r2 = w, w+4, ..., w+28.
        #pragma unroll
        for (int k = 0; k < 8; k++) {
            const int r2  = 4 * k + w;        // L2 output row 0..31
            const int r1a = 2 * r2;           // L1 output rows
            const int r1b = 2 * r2 + 1;

            // 4 independent LDG.128: input rows 4*r2 .. 4*r2+3, float4 at col 4*lane
            const float4* R0 = reinterpret_cast<const float4*>(ip + (long)(4 * r2)     * 512);
            const float4* R1 = reinterpret_cast<const float4*>(ip + (long)(4 * r2 + 1) * 512);
            const float4* R2 = reinterpret_cast<const float4*>(ip + (long)(4 * r2 + 2) * 512);
            const float4* R3 = reinterpret_cast<const float4*>(ip + (long)(4 * r2 + 3) * 512);
            float4 A0 = __ldg(&R0[lane]);
            float4 A1 = __ldg(&R1[lane]);
            float4 B0 = __ldg(&R2[lane]);
            float4 B1 = __ldg(&R3[lane]);

            // L1 row r1a: two output px (cols 2*lane, 2*lane+1)
            float LLa0, LHa0, HLa0, HHa0, LLa1, LHa1, HLa1, HHa1;
            HAAR(A0.x, A0.y, A1.x, A1.y, LLa0, LHa0, HLa0, HHa0);
            HAAR(A0.z, A0.w, A1.z, A1.w, LLa1, LHa1, HLa1, HHa1);
            // L1 row r1b
            float LLb0, LHb0, HLb0, HHb0, LLb1, LHb1, HLb1, HHb1;
            HAAR(B0.x, B0.y, B1.x, B1.y, LLb0, LHb0, HLb0, HHb0);
            HAAR(B0.z, B0.w, B1.z, B1.w, LLb1, LHb1, HLb1, HHb1);

            // Store L1 bands: float2 per lane, 256B contiguous per warp-row
            {
                float* ra = o1 + (long)r1a * 256 + 2 * lane;
                *reinterpret_cast<float2*>(ra)             = make_float2(LLa0, LLa1);
                *reinterpret_cast<float2*>(ra + 65536)     = make_float2(LHa0, LHa1);
                *reinterpret_cast<float2*>(ra + 2 * 65536) = make_float2(HLa0, HLa1);
                *reinterpret_cast<float2*>(ra + 3 * 65536) = make_float2(HHa0, HHa1);
                float* rb = o1 + (long)r1b * 256 + 2 * lane;
                *reinterpret_cast<float2*>(rb)             = make_float2(LLb0, LLb1);
                *reinterpret_cast<float2*>(rb + 65536)     = make_float2(LHb0, LHb1);
                *reinterpret_cast<float2*>(rb + 2 * 65536) = make_float2(HLb0, HLb1);
                *reinterpret_cast<float2*>(rb + 3 * 65536) = make_float2(HHb0, HHb1);
            }

            // Level 2 directly from registers: lane owns the 2x2 LL quad
            //   a = LL[2r2][2l], b = LL[2r2][2l+1], c = LL[2r2+1][2l], d = LL[2r2+1][2l+1]
            float LL2, LH2, HL2, HH2;
            HAAR(LLa0, LLa1, LLb0, LLb1, LL2, LH2, HL2, HH2);

            float* r2p = o2 + (long)r2 * 128 + lane;
            r2p[0]         = LL2;
            r2p[16384]     = LH2;
            r2p[2 * 16384] = HL2;
            r2p[3 * 16384] = HH2;
            s2[r2 * 32 + lane] = LL2;
        }
    }
    __syncthreads();

    // ---- Phase B: Level 3 from s2 (16x16 outputs, 2 px/thread) -----------
    {
        float* o3 = out + S1 + S2 + (long)b * (12 * 4096)
                        + (long)(c * 4) * 4096
                        + (long)(ti * 16) * 64 + tj * 16;

        const int tx = tid & 15;       // 0..15
        const int ty = tid >> 4;       // 0..7
        const float2* s2v = reinterpret_cast<const float2*>(s2);  // 16 f2/row

        #pragma unroll
        for (int r = ty; r < 16; r += 8) {
            float2 t = s2v[(2 * r) * 16 + tx];
            float2 u = s2v[(2 * r + 1) * 16 + tx];

            float LL, LH, HL, HH;
            HAAR(t.x, t.y, u.x, u.y, LL, LH, HL, HH);

            float* orow = o3 + (long)r * 64 + tx;
            orow[0]         = LL;
            orow[4096]      = LH;
            orow[2 * 4096]  = HL;
            orow[3 * 4096]  = HH;
            s3[r * 16 + tx] = LL;
        }
    }
    __syncthreads();

    // ---- Phase C: Level 4 from s3 (8x8 outputs, r/g only) ----------------
    if (tid < 64 && c < 2) {
        float* o4 = out + S1 + S2 + S3 + (long)b * (12 * 1024)
                        + (long)(c * 4) * 1024
                        + (long)(ti * 8) * 32 + tj * 8;

        const int tx = tid & 7;        // 0..7
        const int ty = tid >> 3;       // 0..7
        const float2* s3v = reinterpret_cast<const float2*>(s3);

        float2 t = s3v[(2 * ty) * 8 + tx];
        float2 u = s3v[(2 * ty + 1) * 8 + tx];

        float LL, LH, HL, HH;
        HAAR(t.x, t.y, u.x, u.y, LL, LH, HL, HH);

        float* orow = o4 + (long)ty * 32 + tx;
        orow[0]         = LL;
        orow[1024]      = LH;
        orow[2 * 1024]  = HL;
        orow[3 * 1024]  = HH;

        if (c == 1) {                  // b4 = g4 -> channels 8..11
            float* orow2 = orow + 4 * 1024;
            orow2[0]         = LL;
            orow2[1024]      = LH;
            orow2[2 * 1024]  = HL;
            orow2[3 * 1024]  = HH;
        }
    }
}

extern "C" void kernel_launch(void* const* d_in, const int* in_sizes, int n_in,
                              void* d_out, int out_size)
{
    const float* x = (const float*)d_in[0];
    float* out = (float*)d_out;

    dim3 block(128, 1, 1);
    dim3 grid(4, 4, 96);
    dwt_fused_kernel<<<grid, block>>>(x, out);
}